// round 1
// baseline (speedup 1.0000x reference)
#include <cuda_runtime.h>

// ---------------------------------------------------------------------------
// DeepFM fused pipeline, fp32 CUDA-core baseline.
//
// Stage 1: movie/user embedding GEMMs [16384x512]@[512x256] -> g_dense
//          (movie cols 0..255, user cols 256..511). 257th column handled by
//          a separate tiny kernel into g_add (fm_additive).
// Stage 2: h1 = relu(g_dense @ W1 + b1)   [16384x256]
// Stage 3: h2 = relu(h1 @ W2 + b2)        [16384x128]
// Stage 4: per-row epilogue: out = h2.W3 + b3 + g_add + FM-interaction,
//          where FM-interaction = sum_k (sum_i m[i,k]) * (sum_j u[j,k]).
// ---------------------------------------------------------------------------

#define BATCH 16384

__device__ float g_dense[BATCH * 512];
__device__ float g_add[BATCH];
__device__ float g_h1[BATCH * 256];
__device__ float g_h2[BATCH * 128];

// Tiled SGEMM: C[M x N] = A[M x K] @ W[K x N] + bias (optionally relu).
// Block tile 128x64, BK=16, 256 threads, 8x4 per-thread microtile.
// Assumes M % 128 == 0, N(tile-count*64) <= actual usable cols, K % 16 == 0.
template <bool RELU>
__global__ void __launch_bounds__(256)
gemm128x64(const float* __restrict__ A, const float* __restrict__ W,
           const float* __restrict__ bias, float* __restrict__ C,
           int K, int ldw, int ldc, int col_off)
{
    __shared__ float As[16][128];  // [k][m]
    __shared__ float Bs[16][64];   // [k][n]

    const int tid = threadIdx.x;
    const int m0 = blockIdx.y * 128;
    const int n0 = blockIdx.x * 64;

    // A-tile loader: 128 rows x 16 cols; each thread does 2 float4 loads.
    const int a_row = tid >> 2;          // 0..63
    const int a_col = (tid & 3) << 2;    // 0,4,8,12
    // B-tile loader: 16 rows x 64 cols; one row-quad per thread (scalar loads
    // because ldw may be odd -> float4 would be misaligned).
    const int b_row = tid >> 4;          // 0..15
    const int b_col = (tid & 15) << 2;   // 0..60

    const int ty = tid >> 4;             // 0..15 -> rows ty*8..ty*8+7
    const int tx = tid & 15;             // 0..15 -> cols tx*4..tx*4+3

    float acc[8][4];
#pragma unroll
    for (int i = 0; i < 8; i++)
#pragma unroll
        for (int j = 0; j < 4; j++) acc[i][j] = 0.0f;

    for (int k0 = 0; k0 < K; k0 += 16) {
        float4 av0 = *(const float4*)(A + (m0 + a_row) * K + k0 + a_col);
        float4 av1 = *(const float4*)(A + (m0 + a_row + 64) * K + k0 + a_col);
        As[a_col + 0][a_row] = av0.x;
        As[a_col + 1][a_row] = av0.y;
        As[a_col + 2][a_row] = av0.z;
        As[a_col + 3][a_row] = av0.w;
        As[a_col + 0][a_row + 64] = av1.x;
        As[a_col + 1][a_row + 64] = av1.y;
        As[a_col + 2][a_row + 64] = av1.z;
        As[a_col + 3][a_row + 64] = av1.w;

        const float* wrow = W + (k0 + b_row) * ldw + n0 + b_col;
        Bs[b_row][b_col + 0] = wrow[0];
        Bs[b_row][b_col + 1] = wrow[1];
        Bs[b_row][b_col + 2] = wrow[2];
        Bs[b_row][b_col + 3] = wrow[3];

        __syncthreads();

#pragma unroll
        for (int k = 0; k < 16; k++) {
            float4 a0 = *(const float4*)&As[k][ty * 8];
            float4 a1 = *(const float4*)&As[k][ty * 8 + 4];
            float4 bv = *(const float4*)&Bs[k][tx * 4];
            float av[8] = {a0.x, a0.y, a0.z, a0.w, a1.x, a1.y, a1.z, a1.w};
            float bvv[4] = {bv.x, bv.y, bv.z, bv.w};
#pragma unroll
            for (int i = 0; i < 8; i++)
#pragma unroll
                for (int j = 0; j < 4; j++)
                    acc[i][j] = fmaf(av[i], bvv[j], acc[i][j]);
        }
        __syncthreads();
    }

#pragma unroll
    for (int i = 0; i < 8; i++) {
        const int row = m0 + ty * 8 + i;
#pragma unroll
        for (int j = 0; j < 4; j++) {
            const int col = n0 + tx * 4 + j;
            float v = acc[i][j] + bias[col];
            if (RELU) v = fmaxf(v, 0.0f);
            C[row * ldc + col_off + col] = v;
        }
    }
}

// Column 256 of both embedding towers (the fm_additive term).
// One warp per batch row.
__global__ void __launch_bounds__(256)
extra_col_kernel(const float* __restrict__ mv, const float* __restrict__ uv,
                 const float* __restrict__ Wm, const float* __restrict__ bm,
                 const float* __restrict__ Wu, const float* __restrict__ bu)
{
    const int row = (blockIdx.x * blockDim.x + threadIdx.x) >> 5;
    const int lane = threadIdx.x & 31;
    if (row >= BATCH) return;
    const float* m = mv + row * 512;
    const float* u = uv + row * 512;
    float s = 0.0f;
#pragma unroll 4
    for (int k = lane; k < 512; k += 32)
        s = fmaf(m[k], __ldg(&Wm[k * 257 + 256]),
            fmaf(u[k], __ldg(&Wu[k * 257 + 256]), s));
#pragma unroll
    for (int off = 16; off; off >>= 1)
        s += __shfl_down_sync(0xFFFFFFFFu, s, off);
    if (lane == 0) g_add[row] = s + bm[256] + bu[256];
}

// Final epilogue: W3 dot + b3 + additive + collapsed FM interaction.
// One warp per batch row.
__global__ void __launch_bounds__(256)
final_kernel(const float* __restrict__ W3, const float* __restrict__ b3,
             float* __restrict__ out)
{
    const int row = (blockIdx.x * blockDim.x + threadIdx.x) >> 5;
    const int lane = threadIdx.x & 31;
    if (row >= BATCH) return;

    const float* h2 = g_h2 + row * 128;
    float dot = 0.0f;
#pragma unroll
    for (int j = 0; j < 4; j++)
        dot = fmaf(h2[lane + 32 * j], __ldg(&W3[lane + 32 * j]), dot);

    // FM interaction: sum over all (i,j) pairs of m_i . u_j
    //   = sum_k colsum_m[k] * colsum_u[k],  colsum over the mod-16 lanes.
    // Lanes 0..15 compute colsum_m[lane]; lanes 16..31 compute colsum_u[lane-16].
    const float* d = g_dense + row * 512;
    const int base = (lane < 16) ? lane : (256 + (lane - 16));
    float s = 0.0f;
#pragma unroll
    for (int i = 0; i < 16; i++) s += d[base + i * 16];

    const float partner = __shfl_xor_sync(0xFFFFFFFFu, s, 16);
    const float prod = (lane < 16) ? s * partner : 0.0f;

    float tot = dot + prod;
#pragma unroll
    for (int off = 16; off; off >>= 1)
        tot += __shfl_down_sync(0xFFFFFFFFu, tot, off);
    if (lane == 0) out[row] = tot + b3[0] + g_add[row];
}

extern "C" void kernel_launch(void* const* d_in, const int* in_sizes, int n_in,
                              void* d_out, int out_size)
{
    const float* mv = (const float*)d_in[0];
    const float* uv = (const float*)d_in[1];
    const float* Wm = (const float*)d_in[2];
    const float* bm = (const float*)d_in[3];
    const float* Wu = (const float*)d_in[4];
    const float* bu = (const float*)d_in[5];
    const float* W1 = (const float*)d_in[6];
    const float* b1 = (const float*)d_in[7];
    const float* W2 = (const float*)d_in[8];
    const float* b2 = (const float*)d_in[9];
    const float* W3 = (const float*)d_in[10];
    const float* b3 = (const float*)d_in[11];
    float* out = (float*)d_out;

    float *p_dense, *p_h1, *p_h2;
    cudaGetSymbolAddress((void**)&p_dense, g_dense);
    cudaGetSymbolAddress((void**)&p_h1, g_h1);
    cudaGetSymbolAddress((void**)&p_h2, g_h2);

    const dim3 thr(256);

    // Stage 1: embedding towers (dense 256-col part).
    gemm128x64<false><<<dim3(4, BATCH / 128), thr>>>(mv, Wm, bm, p_dense,
                                                     512, 257, 512, 0);
    gemm128x64<false><<<dim3(4, BATCH / 128), thr>>>(uv, Wu, bu, p_dense,
                                                     512, 257, 512, 256);
    // Additive column (col 256 of each tower).
    extra_col_kernel<<<BATCH / 8, thr>>>(mv, uv, Wm, bm, Wu, bu);

    // Stage 2/3: MLP.
    gemm128x64<true><<<dim3(4, BATCH / 128), thr>>>(p_dense, W1, b1, p_h1,
                                                    512, 256, 256, 0);
    gemm128x64<true><<<dim3(2, BATCH / 128), thr>>>(p_h1, W2, b2, p_h2,
                                                    256, 128, 128, 0);

    // Stage 4: final epilogue.
    final_kernel<<<BATCH / 8, thr>>>(W3, b3, out);
}

// round 5
// speedup vs baseline: 1.9895x; 1.9895x over previous
#include <cuda_runtime.h>
#include <cuda_bf16.h>
#include <cstdint>

#define BATCH 16384

// ---------------- global scratch (__device__, allocation-free) ----------------
__device__ __nv_bfloat16 g_mv_h[BATCH * 512], g_mv_l[BATCH * 512];
__device__ __nv_bfloat16 g_uv_h[BATCH * 512], g_uv_l[BATCH * 512];
__device__ __nv_bfloat16 g_dn_h[BATCH * 512], g_dn_l[BATCH * 512];
__device__ __nv_bfloat16 g_h1_h[BATCH * 256], g_h1_l[BATCH * 256];
__device__ float g_h2[BATCH * 128];
__device__ float g_add[BATCH];
__device__ __nv_bfloat16 g_wmt_h[256 * 512], g_wmt_l[256 * 512];
__device__ __nv_bfloat16 g_wut_h[256 * 512], g_wut_l[256 * 512];
__device__ __nv_bfloat16 g_w1t_h[256 * 512], g_w1t_l[256 * 512];
__device__ __nv_bfloat16 g_w2t_h[128 * 256], g_w2t_l[128 * 256];

// ---------------- helpers ----------------
__device__ __forceinline__ uint32_t smem_u32(const void* p) {
    uint32_t a;
    asm("{ .reg .u64 t; cvta.to.shared.u64 t, %1; cvt.u32.u64 %0, t; }"
        : "=r"(a) : "l"(p));
    return a;
}
__device__ __forceinline__ void cp16(uint32_t s, const void* g) {
    asm volatile("cp.async.cg.shared.global [%0], [%1], 16;" :: "r"(s), "l"(g));
}
__device__ __forceinline__ void cp_commit() {
    asm volatile("cp.async.commit_group;" ::: "memory");
}
template <int N>
__device__ __forceinline__ void cp_wait() {
    asm volatile("cp.async.wait_group %0;" :: "n"(N) : "memory");
}
__device__ __forceinline__ void ldsm4(uint32_t* r, uint32_t a) {
    asm volatile("ldmatrix.sync.aligned.m8n8.x4.shared.b16 {%0,%1,%2,%3}, [%4];"
                 : "=r"(r[0]), "=r"(r[1]), "=r"(r[2]), "=r"(r[3]) : "r"(a));
}
__device__ __forceinline__ void ldsm2(uint32_t* r, uint32_t a) {
    asm volatile("ldmatrix.sync.aligned.m8n8.x2.shared.b16 {%0,%1}, [%2];"
                 : "=r"(r[0]), "=r"(r[1]) : "r"(a));
}
__device__ __forceinline__ void mma16816(float* d, const uint32_t* a, const uint32_t* b) {
    asm volatile(
        "mma.sync.aligned.m16n8k16.row.col.f32.bf16.bf16.f32 "
        "{%0,%1,%2,%3}, {%4,%5,%6,%7}, {%8,%9}, {%0,%1,%2,%3};"
        : "+f"(d[0]), "+f"(d[1]), "+f"(d[2]), "+f"(d[3])
        : "r"(a[0]), "r"(a[1]), "r"(a[2]), "r"(a[3]), "r"(b[0]), "r"(b[1]));
}

// ---------------- activation prep: fp32 -> bf16 hi/lo ----------------
__global__ void __launch_bounds__(256)
prep_act(const float4* __restrict__ X, uint2* __restrict__ H, uint2* __restrict__ L, int n4)
{
    const int i = blockIdx.x * blockDim.x + threadIdx.x;
    if (i >= n4) return;
    const float4 v = X[i];
    const float f[4] = {v.x, v.y, v.z, v.w};
    __nv_bfloat16 h[4], l[4];
#pragma unroll
    for (int j = 0; j < 4; ++j) {
        h[j] = __float2bfloat16(f[j]);
        l[j] = __float2bfloat16(f[j] - __bfloat162float(h[j]));
    }
    uint2 ph, pl;
    ph.x = ((uint32_t)*(uint16_t*)&h[1] << 16) | *(uint16_t*)&h[0];
    ph.y = ((uint32_t)*(uint16_t*)&h[3] << 16) | *(uint16_t*)&h[2];
    pl.x = ((uint32_t)*(uint16_t*)&l[1] << 16) | *(uint16_t*)&l[0];
    pl.y = ((uint32_t)*(uint16_t*)&l[3] << 16) | *(uint16_t*)&l[2];
    H[i] = ph;
    L[i] = pl;
}

// ---------------- weight prep: transpose + hi/lo split ----------------
__global__ void __launch_bounds__(256)
prep_w(const float* __restrict__ W, int ldw, int K,
       __nv_bfloat16* __restrict__ th, __nv_bfloat16* __restrict__ tl)
{
    const int n = blockIdx.x;
    for (int k = threadIdx.x; k < K; k += blockDim.x) {
        const float v = W[(size_t)k * ldw + n];
        const __nv_bfloat16 h = __float2bfloat16(v);
        th[(size_t)n * K + k] = h;
        tl[(size_t)n * K + k] = __float2bfloat16(v - __bfloat162float(h));
    }
}

// ---------------- mma.sync split-bf16 GEMM ----------------
// CTA tile 128x128, BK=32, 256 threads (8 warps as 2m x 4n, warp tile 64x32).
// Smem per stage: 4 tiles [128 rows][32 halves] padded to 40-half stride.
// Byte offsets within a stage: Ah=0, Al=10240, Bh=20480, Bl=30720. Stage=40960B.
template <bool RELU, bool SPLIT>
__global__ void __launch_bounds__(256)
gemm_mma(const __nv_bfloat16* __restrict__ Ah, const __nv_bfloat16* __restrict__ Al, int lda,
         const __nv_bfloat16* __restrict__ Bh, const __nv_bfloat16* __restrict__ Bl, int K,
         const float* __restrict__ bias,
         __nv_bfloat16* __restrict__ Oh, __nv_bfloat16* __restrict__ Ol,
         float* __restrict__ Of, int ldc, int col_off)
{
    extern __shared__ __nv_bfloat16 sm[];
    const uint32_t sbase = smem_u32(sm);
    const int tid = threadIdx.x, lane = tid & 31, wid = tid >> 5;
    const int m0 = blockIdx.x * 128, n0 = blockIdx.y * 128;
    const int wm = wid & 1, wn = wid >> 1;

    // loader mapping: 256 threads, each 2 contiguous 16B chunks of one row
    const int row_ld = tid >> 1;
    const int cp0 = (tid & 1) * 2;                    // chunk index 0 or 2
    const uint32_t s_off = (uint32_t)(row_ld * 40 + cp0 * 8) * 2;  // bytes
    const __nv_bfloat16* gA_h = Ah + (size_t)(m0 + row_ld) * lda + cp0 * 8;
    const __nv_bfloat16* gA_l = Al + (size_t)(m0 + row_ld) * lda + cp0 * 8;
    const __nv_bfloat16* gB_h = Bh + (size_t)(n0 + row_ld) * K + cp0 * 8;
    const __nv_bfloat16* gB_l = Bl + (size_t)(n0 + row_ld) * K + cp0 * 8;

    float acc[4][4][4];
#pragma unroll
    for (int a = 0; a < 4; ++a)
#pragma unroll
        for (int b = 0; b < 4; ++b)
#pragma unroll
            for (int c = 0; c < 4; ++c) acc[a][b][c] = 0.0f;

    const int KCH = K >> 5;

#define ISSUE(kc, buf)                                                      \
    do {                                                                    \
        const uint32_t sb_ = sbase + (buf) * 40960u + s_off;                \
        const int ko_ = (kc) << 5;                                          \
        cp16(sb_ + 0u,      gA_h + ko_);                                    \
        cp16(sb_ + 16u,     gA_h + ko_ + 8);                                \
        cp16(sb_ + 10240u,  gA_l + ko_);                                    \
        cp16(sb_ + 10256u,  gA_l + ko_ + 8);                                \
        cp16(sb_ + 20480u,  gB_h + ko_);                                    \
        cp16(sb_ + 20496u,  gB_h + ko_ + 8);                                \
        cp16(sb_ + 30720u,  gB_l + ko_);                                    \
        cp16(sb_ + 30736u,  gB_l + ko_ + 8);                                \
        cp_commit();                                                        \
    } while (0)

    ISSUE(0, 0);

    // ldmatrix address components (constant across k-chunks)
    const int a_row = wm * 64 + (lane & 15);
    const int a_khi = (lane >> 4) << 3;
    const int l16 = lane & 15;
    const int b_row = wn * 32 + (l16 & 7);
    const int b_khi = (l16 >> 3) << 3;

    for (int kc = 0; kc < KCH; ++kc) {
        if (kc + 1 < KCH) {
            ISSUE(kc + 1, (kc + 1) & 1);
            cp_wait<1>();
        } else {
            cp_wait<0>();
        }
        __syncthreads();

        const uint32_t ab = sbase + (kc & 1) * 40960u;
#pragma unroll
        for (int ks = 0; ks < 32; ks += 16) {
            uint32_t fah[4][4], fal[4][4], fbh[4][2], fbl[4][2];
#pragma unroll
            for (int mf = 0; mf < 4; ++mf) {
                const uint32_t aa = ab + (uint32_t)((a_row + mf * 16) * 40 + ks + a_khi) * 2;
                ldsm4(fah[mf], aa);
                ldsm4(fal[mf], aa + 10240u);
            }
#pragma unroll
            for (int nf = 0; nf < 4; ++nf) {
                const uint32_t ba = ab + 20480u + (uint32_t)((b_row + nf * 8) * 40 + ks + b_khi) * 2;
                ldsm2(fbh[nf], ba);
                ldsm2(fbl[nf], ba + 10240u);
            }
#pragma unroll
            for (int mf = 0; mf < 4; ++mf)
#pragma unroll
                for (int nf = 0; nf < 4; ++nf) {
                    mma16816(acc[mf][nf], fah[mf], fbh[nf]);
                    mma16816(acc[mf][nf], fah[mf], fbl[nf]);
                    mma16816(acc[mf][nf], fal[mf], fbh[nf]);
                }
        }
        __syncthreads();
    }
#undef ISSUE

    // ---------------- epilogue ----------------
    const int r_base = m0 + wm * 64 + (lane >> 2);
    const int c_base = n0 + wn * 32 + 2 * (lane & 3);
#pragma unroll
    for (int mf = 0; mf < 4; ++mf) {
#pragma unroll
        for (int nf = 0; nf < 4; ++nf) {
            const int c = c_base + nf * 8;
            const float b0 = __ldg(&bias[c]);
            const float b1 = __ldg(&bias[c + 1]);
#pragma unroll
            for (int half = 0; half < 2; ++half) {
                const int r = r_base + mf * 16 + half * 8;
                float v0 = acc[mf][nf][2 * half + 0] + b0;
                float v1 = acc[mf][nf][2 * half + 1] + b1;
                if (RELU) { v0 = fmaxf(v0, 0.0f); v1 = fmaxf(v1, 0.0f); }
                if (SPLIT) {
                    const __nv_bfloat16 h0 = __float2bfloat16(v0);
                    const __nv_bfloat16 h1 = __float2bfloat16(v1);
                    const __nv_bfloat16 q0 = __float2bfloat16(v0 - __bfloat162float(h0));
                    const __nv_bfloat16 q1 = __float2bfloat16(v1 - __bfloat162float(h1));
                    const uint32_t ph = ((uint32_t)*(const uint16_t*)&h1 << 16) |
                                        *(const uint16_t*)&h0;
                    const uint32_t pl = ((uint32_t)*(const uint16_t*)&q1 << 16) |
                                        *(const uint16_t*)&q0;
                    const size_t idx = (size_t)r * ldc + col_off + c;
                    *(uint32_t*)(Oh + idx) = ph;
                    *(uint32_t*)(Ol + idx) = pl;
                } else {
                    float2 o; o.x = v0; o.y = v1;
                    *(float2*)(Of + (size_t)r * ldc + col_off + c) = o;
                }
            }
        }
    }
}

// ---------------- fm_additive: column 256 of both towers ----------------
__global__ void __launch_bounds__(256)
extra_col_kernel(const float* __restrict__ mv, const float* __restrict__ uv,
                 const float* __restrict__ Wm, const float* __restrict__ bm,
                 const float* __restrict__ Wu, const float* __restrict__ bu)
{
    const int row = (blockIdx.x * blockDim.x + threadIdx.x) >> 5;
    const int lane = threadIdx.x & 31;
    if (row >= BATCH) return;
    const float* m = mv + (size_t)row * 512;
    const float* u = uv + (size_t)row * 512;
    float s = 0.0f;
#pragma unroll 4
    for (int k = lane; k < 512; k += 32)
        s = fmaf(m[k], __ldg(&Wm[(size_t)k * 257 + 256]),
            fmaf(u[k], __ldg(&Wu[(size_t)k * 257 + 256]), s));
#pragma unroll
    for (int off = 16; off; off >>= 1) s += __shfl_down_sync(0xFFFFFFFFu, s, off);
    if (lane == 0) g_add[row] = s + bm[256] + bu[256];
}

// ---------------- final epilogue ----------------
// out = h2.W3 + b3 + additive + FM, where FM = sum_k msum_k * usum_k
// (msum/usum = mod-16 column sums of the dense embedding row).
__global__ void __launch_bounds__(256)
final_kernel(const float* __restrict__ W3, const float* __restrict__ b3,
             float* __restrict__ out)
{
    const int row = (blockIdx.x * blockDim.x + threadIdx.x) >> 5;
    const int lane = threadIdx.x & 31;
    if (row >= BATCH) return;

    const float* h2 = g_h2 + (size_t)row * 128;
    float tot = 0.0f;
#pragma unroll
    for (int j = 0; j < 4; ++j)
        tot = fmaf(h2[lane + 32 * j], __ldg(&W3[lane + 32 * j]), tot);

    // lanes 0..15 -> movie class l (cols l+16i); lanes 16..31 -> user class.
    const int l = lane & 15;
    const size_t base = (size_t)row * 512 + (lane >= 16 ? 256 : 0);
    float s = 0.0f;
#pragma unroll
    for (int i = 0; i < 16; ++i) {
        const int c = l + 16 * i;
        s += __bfloat162float(g_dn_h[base + c]) + __bfloat162float(g_dn_l[base + c]);
    }
    const float partner = __shfl_xor_sync(0xFFFFFFFFu, s, 16);
    if (lane < 16) tot += s * partner;

#pragma unroll
    for (int off = 16; off; off >>= 1) tot += __shfl_down_sync(0xFFFFFFFFu, tot, off);
    if (lane == 0) out[row] = tot + b3[0] + g_add[row];
}

// ---------------- launch ----------------
extern "C" void kernel_launch(void* const* d_in, const int* in_sizes, int n_in,
                              void* d_out, int out_size)
{
    const float* mv = (const float*)d_in[0];
    const float* uv = (const float*)d_in[1];
    const float* Wm = (const float*)d_in[2];
    const float* bm = (const float*)d_in[3];
    const float* Wu = (const float*)d_in[4];
    const float* bu = (const float*)d_in[5];
    const float* W1 = (const float*)d_in[6];
    const float* b1 = (const float*)d_in[7];
    const float* W2 = (const float*)d_in[8];
    const float* b2 = (const float*)d_in[9];
    const float* W3 = (const float*)d_in[10];
    const float* b3 = (const float*)d_in[11];
    float* out = (float*)d_out;

    __nv_bfloat16 *p_mv_h, *p_mv_l, *p_uv_h, *p_uv_l;
    __nv_bfloat16 *p_dn_h, *p_dn_l, *p_h1_h, *p_h1_l;
    float* p_h2;
    __nv_bfloat16 *p_wmt_h, *p_wmt_l, *p_wut_h, *p_wut_l;
    __nv_bfloat16 *p_w1t_h, *p_w1t_l, *p_w2t_h, *p_w2t_l;
    cudaGetSymbolAddress((void**)&p_mv_h, g_mv_h);
    cudaGetSymbolAddress((void**)&p_mv_l, g_mv_l);
    cudaGetSymbolAddress((void**)&p_uv_h, g_uv_h);
    cudaGetSymbolAddress((void**)&p_uv_l, g_uv_l);
    cudaGetSymbolAddress((void**)&p_dn_h, g_dn_h);
    cudaGetSymbolAddress((void**)&p_dn_l, g_dn_l);
    cudaGetSymbolAddress((void**)&p_h1_h, g_h1_h);
    cudaGetSymbolAddress((void**)&p_h1_l, g_h1_l);
    cudaGetSymbolAddress((void**)&p_h2, g_h2);
    cudaGetSymbolAddress((void**)&p_wmt_h, g_wmt_h);
    cudaGetSymbolAddress((void**)&p_wmt_l, g_wmt_l);
    cudaGetSymbolAddress((void**)&p_wut_h, g_wut_h);
    cudaGetSymbolAddress((void**)&p_wut_l, g_wut_l);
    cudaGetSymbolAddress((void**)&p_w1t_h, g_w1t_h);
    cudaGetSymbolAddress((void**)&p_w1t_l, g_w1t_l);
    cudaGetSymbolAddress((void**)&p_w2t_h, g_w2t_h);
    cudaGetSymbolAddress((void**)&p_w2t_l, g_w2t_l);

    constexpr int SMEM = 81920;
    cudaFuncSetAttribute(gemm_mma<false, true>,
                         cudaFuncAttributeMaxDynamicSharedMemorySize, SMEM);
    cudaFuncSetAttribute(gemm_mma<true, true>,
                         cudaFuncAttributeMaxDynamicSharedMemorySize, SMEM);
    cudaFuncSetAttribute(gemm_mma<true, false>,
                         cudaFuncAttributeMaxDynamicSharedMemorySize, SMEM);

    // ---- prep ----
    const int n4 = BATCH * 512 / 4;
    prep_act<<<n4 / 256, 256>>>((const float4*)mv, (uint2*)p_mv_h, (uint2*)p_mv_l, n4);
    prep_act<<<n4 / 256, 256>>>((const float4*)uv, (uint2*)p_uv_h, (uint2*)p_uv_l, n4);
    prep_w<<<256, 256>>>(Wm, 257, 512, p_wmt_h, p_wmt_l);
    prep_w<<<256, 256>>>(Wu, 257, 512, p_wut_h, p_wut_l);
    prep_w<<<256, 256>>>(W1, 256, 512, p_w1t_h, p_w1t_l);
    prep_w<<<128, 256>>>(W2, 128, 256, p_w2t_h, p_w2t_l);
    extra_col_kernel<<<BATCH / 8, 256>>>(mv, uv, Wm, bm, Wu, bu);

    // ---- embedding towers -> g_dense (bf16 hi/lo) ----
    gemm_mma<false, true><<<dim3(BATCH / 128, 2), 256, SMEM>>>(
        p_mv_h, p_mv_l, 512, p_wmt_h, p_wmt_l, 512, bm,
        p_dn_h, p_dn_l, nullptr, 512, 0);
    gemm_mma<false, true><<<dim3(BATCH / 128, 2), 256, SMEM>>>(
        p_uv_h, p_uv_l, 512, p_wut_h, p_wut_l, 512, bu,
        p_dn_h, p_dn_l, nullptr, 512, 256);

    // ---- MLP ----
    gemm_mma<true, true><<<dim3(BATCH / 128, 2), 256, SMEM>>>(
        p_dn_h, p_dn_l, 512, p_w1t_h, p_w1t_l, 512, b1,
        p_h1_h, p_h1_l, nullptr, 256, 0);
    gemm_mma<true, false><<<dim3(BATCH / 128, 1), 256, SMEM>>>(
        p_h1_h, p_h1_l, 256, p_w2t_h, p_w2t_l, 256, b2,
        nullptr, nullptr, p_h2, 128, 0);

    // ---- final ----
    final_kernel<<<BATCH / 8, 256>>>(W3, b3, out);
}